// round 4
// baseline (speedup 1.0000x reference)
#include <cuda_runtime.h>
#include <math.h>

#define FULL 0xffffffffu
typedef unsigned long long u64;
typedef unsigned int u32;

static constexpr int P    = 16;
static constexpr int MAXB = 16384;
static constexpr int NP   = 4;       // paths per warp (fits in 128 regs, no spills)
static constexpr int NBLK = 296;     // persistent grid (148 SMs x 2 CTA)

// ---------------- scratch (__device__ globals; no allocations) ----------------
__device__ float4 g_Utab0[MAXB * 32];
__device__ float4 g_Utab1[MAXB * 32];
__device__ float4 g_Rtab0[32 * 32];
__device__ float4 g_Etab0[32 * 32];
__device__ float4 g_Rtab1[32 * 32];
__device__ float4 g_Etab1[32 * 32];
__device__ float  g_part0[MAXB * 4 * 32];   // per-(b, quad) partial sums of h
__device__ float  g_part1[MAXB * 4 * 32];
__device__ float  g_lossblk[NBLK];

// fast tanh (1 MUFU) and sigmoid built on it (1 MUFU + 1 FMA)
__device__ __forceinline__ float tanha(float x) {
    float y; asm("tanh.approx.f32 %0,%1;" : "=f"(y) : "f"(x)); return y;
}
__device__ __forceinline__ float sigf(float x) {
    return fmaf(tanha(0.5f * x), 0.5f, 0.5f);
}

__device__ __forceinline__ u64 ffma2(u64 a, u64 b, u64 c) {
    u64 d; asm("fma.rn.f32x2 %0,%1,%2,%3;" : "=l"(d) : "l"(a), "l"(b), "l"(c)); return d;
}
__device__ __forceinline__ u64 fadd2(u64 a, u64 b) {
    u64 d; asm("add.rn.f32x2 %0,%1,%2;" : "=l"(d) : "l"(a), "l"(b)); return d;
}
__device__ __forceinline__ u64 pack2(float x) {
    u64 d; asm("mov.b64 %0,{%1,%1};" : "=l"(d) : "f"(x)); return d;
}
__device__ __forceinline__ u64 pack2f(float x, float y) {
    u64 d; asm("mov.b64 %0,{%1,%2};" : "=l"(d) : "f"(x), "f"(y)); return d;
}
__device__ __forceinline__ float2 unpack2(u64 a) {
    float2 f; asm("mov.b64 {%0,%1},%2;" : "=f"(f.x), "=f"(f.y) : "l"(a)); return f;
}

// ---------------- precompute E/R contribution tables (tiny) ----------------
__global__ void precompute_tables_kernel(const float* __restrict__ rel_table,
                                         const float* __restrict__ ent_table,
                                         const float* __restrict__ wih0,
                                         const float* __restrict__ wih1) {
    int tid   = threadIdx.x;          // 1024
    int which = blockIdx.x;           // 0:Rtab0 1:Etab0 2:Rtab1 3:Etab1
    int r     = tid >> 5;
    int lane  = tid & 31;
    const float* w   = (which < 2) ? wih0 : wih1;
    const float* src = (which & 1) ? ent_table : rel_table;
    int colofs       = (which & 1) ? 32 : 0;

    float4 acc = make_float4(0.f, 0.f, 0.f, 0.f);
    #pragma unroll
    for (int k = 0; k < 32; k++) {
        float x = src[r * 32 + k];
        acc.x += x * w[(0 * 32 + lane) * 64 + colofs + k];
        acc.y += x * w[(1 * 32 + lane) * 64 + colofs + k];
        acc.z += x * w[(2 * 32 + lane) * 64 + colofs + k];
        acc.w += x * w[(3 * 32 + lane) * 64 + colofs + k];
    }
    float4* dst = (which == 0) ? g_Rtab0 : (which == 1) ? g_Etab0
                : (which == 2) ? g_Rtab1 : g_Etab1;
    dst[tid] = acc;
}

// ---------------- precompute per-b user contribution (persistent grid) ----------------
__global__ __launch_bounds__(256) void precompute_u_kernel(
        const float* __restrict__ user_table,
        const float* __restrict__ wih0,
        const float* __restrict__ wih1,
        const int* __restrict__ users, int B) {
    __shared__ float4 w0[32 * 32];
    __shared__ float4 w1[32 * 32];
    int tid = threadIdx.x;
    for (int i = tid; i < 32 * 32; i += 256) {
        int k = i >> 5, l = i & 31;
        w0[i] = make_float4(wih0[l * 64 + k], wih0[(l + 32) * 64 + k],
                            wih0[(l + 64) * 64 + k], wih0[(l + 96) * 64 + k]);
        w1[i] = make_float4(wih1[l * 64 + k], wih1[(l + 32) * 64 + k],
                            wih1[(l + 64) * 64 + k], wih1[(l + 96) * 64 + k]);
    }
    __syncthreads();

    int wid = tid >> 5, lane = tid & 31;
    int gw = blockIdx.x * 8 + wid, TW = gridDim.x * 8;
    for (int b = gw; b < B; b += TW) {
        float u = user_table[users[b] * 32 + lane];
        float4 a0 = make_float4(0.f, 0.f, 0.f, 0.f);
        float4 a1 = make_float4(0.f, 0.f, 0.f, 0.f);
        #pragma unroll
        for (int k = 0; k < 32; k++) {
            float uk = __shfl_sync(FULL, u, k);
            float4 q0 = w0[k * 32 + lane];
            float4 q1 = w1[k * 32 + lane];
            a0.x += uk * q0.x; a0.y += uk * q0.y; a0.z += uk * q0.z; a0.w += uk * q0.w;
            a1.x += uk * q1.x; a1.y += uk * q1.y; a1.z += uk * q1.z; a1.w += uk * q1.w;
        }
        g_Utab0[b * 32 + lane] = a0;
        g_Utab1[b * 32 + lane] = a1;
    }
}

// ---------------- main hop kernel: NP=4 paths/warp, pre-packed h, f32x2 FFMAs ----------------
template <int NSTEP, int STRIDE, int HOP>
__global__ __launch_bounds__(256, 2) void hop_kernel(
        const float* __restrict__ whh,
        const float* __restrict__ b_ih,
        const float* __restrict__ b_hh,
        const int* __restrict__ items,
        const int* __restrict__ lp, int B) {
    __shared__ ulonglong2 whh_sm[32 * 32];   // 16 KB: [k][lane] -> 4 gate weights
    __shared__ u64 hp_sm[8 * NP * 32];       // 8 KB: per-warp packed {h,h}

    int tid = threadIdx.x, wid = tid >> 5, lane = tid & 31;
    for (int i = tid; i < 32 * 32; i += 256) {
        int k = i >> 5, l = i & 31;
        float4 w4 = make_float4(whh[l * 32 + k], whh[(l + 32) * 32 + k],
                                whh[(l + 64) * 32 + k], whh[(l + 96) * 32 + k]);
        whh_sm[i] = *reinterpret_cast<ulonglong2*>(&w4);
    }
    __syncthreads();

    const ulonglong2* Utab = reinterpret_cast<const ulonglong2*>(HOP ? g_Utab1 : g_Utab0);
    const ulonglong2* Rtab = reinterpret_cast<const ulonglong2*>(HOP ? g_Rtab1 : g_Rtab0);
    const ulonglong2* Etab = reinterpret_cast<const ulonglong2*>(HOP ? g_Etab1 : g_Etab0);
    float* gpart = HOP ? g_part1 : g_part0;

    u64 bias_lo = pack2f(b_ih[lane]      + b_hh[lane],      b_ih[32 + lane] + b_hh[32 + lane]);
    u64 bias_hi = pack2f(b_ih[64 + lane] + b_hh[64 + lane], b_ih[96 + lane] + b_hh[96 + lane]);

    u64* hpw = hp_sm + wid * (NP * 32);

    int gw = blockIdx.x * 8 + wid;
    int TW = NBLK * 8;
    int ntask = B * 4;                       // task = (b, quad of 4 paths)

    for (int task = gw; task < ntask; task += TW) {
        int b = task >> 2, quad = task & 3;
        int item = __ldg(&items[b]);
        const int* lpb = lp + (size_t)item * (P * STRIDE) + (size_t)quad * (NP * STRIDE);

        // pack indices: 5 bits each (values in [0,32))
        u32 ipack[NP];
        #pragma unroll
        for (int p = 0; p < NP; p++) {
            u32 v = 0;
            #pragma unroll
            for (int j = 0; j < STRIDE; j++)
                v |= ((u32)__ldg(&lpb[p * STRIDE + j])) << (5 * j);
            ipack[p] = v;
        }

        ulonglong2 Ub = Utab[b * 32 + lane];
        u64 base_lo = fadd2(bias_lo, Ub.x);
        u64 base_hi = fadd2(bias_hi, Ub.y);

        // ---- step 0: gates = bias + U[b] + E[seed]; (h,c)=0 before ----
        float c[NP], h[NP];
        #pragma unroll
        for (int p = 0; p < NP; p++) {
            ulonglong2 E = Etab[(ipack[p] & 31) * 32 + lane];
            float2 glo = unpack2(fadd2(base_lo, E.x));   // (i, f)
            float2 ghi = unpack2(fadd2(base_hi, E.y));   // (g, o)
            c[p] = sigf(glo.x) * tanha(ghi.x);
            h[p] = sigf(ghi.y) * tanha(c[p]);
        }

        // ---- steps 1..NSTEP-1: gates = bias + R + T + h @ W_hh^T ----
        #pragma unroll
        for (int s = 1; s < NSTEP; s++) {
            __syncwarp();
            #pragma unroll
            for (int p = 0; p < NP; p++)
                hpw[p * 32 + lane] = pack2(h[p]);        // STS.64 {h,h}
            __syncwarp();

            u64 Blo[NP], Bhi[NP];
            #pragma unroll
            for (int p = 0; p < NP; p++) {
                int ri = (ipack[p] >> (5 * (2 * s - 1))) & 31;
                int ti = (ipack[p] >> (5 * (2 * s)))     & 31;
                ulonglong2 R = Rtab[ri * 32 + lane];
                ulonglong2 T = Etab[ti * 32 + lane];
                Blo[p] = fadd2(fadd2(bias_lo, R.x), T.x);
                Bhi[p] = fadd2(fadd2(bias_hi, R.y), T.y);
            }
            #pragma unroll
            for (int j = 0; j < 8; j++) {
                ulonglong2 w0 = whh_sm[(4 * j + 0) * 32 + lane];
                ulonglong2 w1 = whh_sm[(4 * j + 1) * 32 + lane];
                ulonglong2 w2 = whh_sm[(4 * j + 2) * 32 + lane];
                ulonglong2 w3 = whh_sm[(4 * j + 3) * 32 + lane];
                #pragma unroll
                for (int p = 0; p < NP; p++) {
                    ulonglong2 ha = *reinterpret_cast<ulonglong2*>(&hpw[p * 32 + 4 * j]);
                    ulonglong2 hb = *reinterpret_cast<ulonglong2*>(&hpw[p * 32 + 4 * j + 2]);
                    Blo[p] = ffma2(ha.x, w0.x, Blo[p]); Bhi[p] = ffma2(ha.x, w0.y, Bhi[p]);
                    Blo[p] = ffma2(ha.y, w1.x, Blo[p]); Bhi[p] = ffma2(ha.y, w1.y, Bhi[p]);
                    Blo[p] = ffma2(hb.x, w2.x, Blo[p]); Bhi[p] = ffma2(hb.x, w2.y, Bhi[p]);
                    Blo[p] = ffma2(hb.y, w3.x, Blo[p]); Bhi[p] = ffma2(hb.y, w3.y, Bhi[p]);
                }
            }
            #pragma unroll
            for (int p = 0; p < NP; p++) {
                float2 glo = unpack2(Blo[p]);   // (i, f)
                float2 ghi = unpack2(Bhi[p]);   // (g, o)
                c[p] = sigf(glo.y) * c[p] + sigf(glo.x) * tanha(ghi.x);
                h[p] = sigf(ghi.y) * tanha(c[p]);
            }
        }

        gpart[task * 32 + lane] = h[0] + h[1] + h[2] + h[3];
    }
}

// ---------------- combine: agg matmuls, scores, sigmoid, block loss partials ----------------
__global__ __launch_bounds__(256) void combine_kernel(
        const float* __restrict__ user_table,
        const float* __restrict__ ent_table,
        const float* __restrict__ agg_w,
        const float* __restrict__ agg_b,
        const int* __restrict__ users,
        const int* __restrict__ items,
        const int* __restrict__ ratings,
        float* __restrict__ out, int B) {
    __shared__ float aggT[32 * 32];
    __shared__ float aggb_sm[32];
    __shared__ float lred[8];
    int tid = threadIdx.x;
    for (int i = tid; i < 32 * 32; i += 256) {
        int k = i >> 5, j = i & 31;
        aggT[i] = agg_w[j * 32 + k];
    }
    if (tid < 32) aggb_sm[tid] = agg_b[tid];
    __syncthreads();

    int wid = tid >> 5, lane = tid & 31;
    int gw = blockIdx.x * 8 + wid, TW = gridDim.x * 8;
    float loss_acc = 0.f;

    for (int b = gw; b < B; b += TW) {
        int item = items[b];
        int user = users[b];

        float f0 = 0.f, f1 = 0.f;
        #pragma unroll
        for (int q = 0; q < 4; q++) {
            f0 += g_part0[(b * 4 + q) * 32 + lane];
            f1 += g_part1[(b * 4 + q) * 32 + lane];
        }

        // hop-0 aggregation: emb1 = (ent[item] + final0) @ agg_w^T + agg_b
        float v = ent_table[item * 32 + lane] + f0;
        float acc = aggb_sm[lane];
        #pragma unroll
        for (int k = 0; k < 32; k++)
            acc += __shfl_sync(FULL, v, k) * aggT[k * 32 + lane];

        // hop-1 aggregation
        v = acc + f1;
        acc = aggb_sm[lane];
        #pragma unroll
        for (int k = 0; k < 32; k++)
            acc += __shfl_sync(FULL, v, k) * aggT[k * 32 + lane];

        // score = dot(u, emb2)
        float prod = user_table[user * 32 + lane] * acc;
        #pragma unroll
        for (int o = 16; o; o >>= 1) prod += __shfl_xor_sync(FULL, prod, o);

        if (lane == 0) {
            float s = prod;
            out[1 + b]     = 1.0f / (1.0f + __expf(-s));
            out[1 + B + b] = (float)item;
            float r    = (float)ratings[b];
            float ls_p = fminf(s, 0.0f)  - log1pf(__expf(-fabsf(s)));
            float ls_n = fminf(-s, 0.0f) - log1pf(__expf(-fabsf(s)));
            loss_acc += -(r * ls_p + (1.0f - r) * ls_n);
        }
    }

    if (lane == 0) lred[wid] = loss_acc;
    __syncthreads();
    if (tid == 0) {
        float s = 0.f;
        #pragma unroll
        for (int w = 0; w < 8; w++) s += lred[w];
        g_lossblk[blockIdx.x] = s;
    }
}

// ---------------- final loss reduction ----------------
__global__ void loss_kernel(float* __restrict__ out, int B, int nblk) {
    __shared__ float sm[512];
    int tid = threadIdx.x;
    float s = 0.f;
    for (int i = tid; i < nblk; i += 512) s += g_lossblk[i];
    sm[tid] = s;
    __syncthreads();
    for (int o = 256; o; o >>= 1) {
        if (tid < o) sm[tid] += sm[tid + o];
        __syncthreads();
    }
    if (tid == 0) out[0] = sm[0] / (float)B;
}

// ---------------- launch ----------------
extern "C" void kernel_launch(void* const* d_in, const int* in_sizes, int n_in,
                              void* d_out, int out_size) {
    const float* user_table = (const float*)d_in[0];
    const float* ent_table  = (const float*)d_in[1];
    const float* rel_table  = (const float*)d_in[2];
    const float* w_ih0      = (const float*)d_in[3];
    const float* w_hh0      = (const float*)d_in[4];
    const float* b_ih0      = (const float*)d_in[5];
    const float* b_hh0      = (const float*)d_in[6];
    const float* w_ih1      = (const float*)d_in[7];
    const float* w_hh1      = (const float*)d_in[8];
    const float* b_ih1      = (const float*)d_in[9];
    const float* b_hh1      = (const float*)d_in[10];
    const float* agg_w      = (const float*)d_in[11];
    const float* agg_b      = (const float*)d_in[12];
    const int*   users      = (const int*)d_in[13];
    const int*   items      = (const int*)d_in[14];
    const int*   ratings    = (const int*)d_in[15];
    const int*   lp0        = (const int*)d_in[16];
    const int*   lp1        = (const int*)d_in[17];
    float*       out        = (float*)d_out;

    int B = in_sizes[13];

    precompute_tables_kernel<<<4, 1024>>>(rel_table, ent_table, w_ih0, w_ih1);
    precompute_u_kernel<<<NBLK, 256>>>(user_table, w_ih0, w_ih1, users, B);
    hop_kernel<2, 3, 0><<<NBLK, 256>>>(w_hh0, b_ih0, b_hh0, items, lp0, B);
    hop_kernel<3, 5, 1><<<NBLK, 256>>>(w_hh1, b_ih1, b_hh1, items, lp1, B);
    combine_kernel<<<NBLK, 256>>>(user_table, ent_table, agg_w, agg_b,
                                  users, items, ratings, out, B);
    loss_kernel<<<1, 512>>>(out, B, NBLK);
}

// round 5
// speedup vs baseline: 1.2608x; 1.2608x over previous
#include <cuda_runtime.h>
#include <math.h>

#define FULL 0xffffffffu
typedef unsigned long long u64;
typedef unsigned int u32;

static constexpr int P    = 16;
static constexpr int MAXB = 16384;
static constexpr int NP   = 8;       // paths per warp
static constexpr int NBLK = 296;     // persistent grid (148 SMs x 2 CTA)

// ---------------- scratch (__device__ globals; no allocations) ----------------
__device__ float4 g_Utab0[MAXB * 32];   // bias + u @ W_ih[:, :32]^T  (bias folded in)
__device__ float4 g_Utab1[MAXB * 32];
__device__ float4 g_Rtab0[32 * 32];     // bias + rel @ W_ih[:, :32]^T (bias folded in)
__device__ float4 g_Etab0[32 * 32];     // ent @ W_ih[:, 32:]^T        (no bias)
__device__ float4 g_Rtab1[32 * 32];
__device__ float4 g_Etab1[32 * 32];
__device__ float  g_part0[MAXB * 2 * 32];   // per-(b, half) partial sums of h
__device__ float  g_part1[MAXB * 2 * 32];
__device__ float  g_lossblk[NBLK];

// fast tanh (1 MUFU) and sigmoid built on it (1 MUFU + 1 FMA)
__device__ __forceinline__ float tanha(float x) {
    float y; asm("tanh.approx.f32 %0,%1;" : "=f"(y) : "f"(x)); return y;
}
__device__ __forceinline__ float sigf(float x) {
    return fmaf(tanha(0.5f * x), 0.5f, 0.5f);
}

__device__ __forceinline__ u64 ffma2(u64 a, u64 b, u64 c) {
    u64 d; asm("fma.rn.f32x2 %0,%1,%2,%3;" : "=l"(d) : "l"(a), "l"(b), "l"(c)); return d;
}
__device__ __forceinline__ u64 fadd2(u64 a, u64 b) {
    u64 d; asm("add.rn.f32x2 %0,%1,%2;" : "=l"(d) : "l"(a), "l"(b)); return d;
}
__device__ __forceinline__ u64 pack2(float x) {
    u64 d; asm("mov.b64 %0,{%1,%1};" : "=l"(d) : "f"(x)); return d;
}
__device__ __forceinline__ float2 unpack2(u64 a) {
    float2 f; asm("mov.b64 {%0,%1},%2;" : "=f"(f.x), "=f"(f.y) : "l"(a)); return f;
}

// ---------------- precompute E/R contribution tables (tiny) ----------------
// blockIdx.x: 0:Rtab0(+bias0) 1:Etab0 2:Rtab1(+bias1) 3:Etab1
__global__ void precompute_tables_kernel(const float* __restrict__ rel_table,
                                         const float* __restrict__ ent_table,
                                         const float* __restrict__ wih0,
                                         const float* __restrict__ wih1,
                                         const float* __restrict__ bih0,
                                         const float* __restrict__ bhh0,
                                         const float* __restrict__ bih1,
                                         const float* __restrict__ bhh1) {
    int tid   = threadIdx.x;          // 1024
    int which = blockIdx.x;
    int r     = tid >> 5;
    int lane  = tid & 31;
    const float* w   = (which < 2) ? wih0 : wih1;
    const float* src = (which & 1) ? ent_table : rel_table;
    int colofs       = (which & 1) ? 32 : 0;

    float4 acc = make_float4(0.f, 0.f, 0.f, 0.f);
    if (!(which & 1)) {  // Rtab: fold bias in
        const float* bi = (which < 2) ? bih0 : bih1;
        const float* bh = (which < 2) ? bhh0 : bhh1;
        acc.x = bi[lane]      + bh[lane];
        acc.y = bi[32 + lane] + bh[32 + lane];
        acc.z = bi[64 + lane] + bh[64 + lane];
        acc.w = bi[96 + lane] + bh[96 + lane];
    }
    #pragma unroll
    for (int k = 0; k < 32; k++) {
        float x = src[r * 32 + k];
        acc.x += x * w[(0 * 32 + lane) * 64 + colofs + k];
        acc.y += x * w[(1 * 32 + lane) * 64 + colofs + k];
        acc.z += x * w[(2 * 32 + lane) * 64 + colofs + k];
        acc.w += x * w[(3 * 32 + lane) * 64 + colofs + k];
    }
    float4* dst = (which == 0) ? g_Rtab0 : (which == 1) ? g_Etab0
                : (which == 2) ? g_Rtab1 : g_Etab1;
    dst[tid] = acc;
}

// ---------------- precompute per-b user contribution (bias folded in) ----------------
__global__ __launch_bounds__(256) void precompute_u_kernel(
        const float* __restrict__ user_table,
        const float* __restrict__ wih0,
        const float* __restrict__ wih1,
        const float* __restrict__ bih0,
        const float* __restrict__ bhh0,
        const float* __restrict__ bih1,
        const float* __restrict__ bhh1,
        const int* __restrict__ users, int B) {
    __shared__ float4 w0[32 * 32];
    __shared__ float4 w1[32 * 32];
    int tid = threadIdx.x;
    for (int i = tid; i < 32 * 32; i += 256) {
        int k = i >> 5, l = i & 31;
        w0[i] = make_float4(wih0[l * 64 + k], wih0[(l + 32) * 64 + k],
                            wih0[(l + 64) * 64 + k], wih0[(l + 96) * 64 + k]);
        w1[i] = make_float4(wih1[l * 64 + k], wih1[(l + 32) * 64 + k],
                            wih1[(l + 64) * 64 + k], wih1[(l + 96) * 64 + k]);
    }
    __syncthreads();

    int wid = tid >> 5, lane = tid & 31;
    float4 bias0 = make_float4(bih0[lane]      + bhh0[lane],
                               bih0[32 + lane] + bhh0[32 + lane],
                               bih0[64 + lane] + bhh0[64 + lane],
                               bih0[96 + lane] + bhh0[96 + lane]);
    float4 bias1 = make_float4(bih1[lane]      + bhh1[lane],
                               bih1[32 + lane] + bhh1[32 + lane],
                               bih1[64 + lane] + bhh1[64 + lane],
                               bih1[96 + lane] + bhh1[96 + lane]);

    int gw = blockIdx.x * 8 + wid, TW = gridDim.x * 8;
    for (int b = gw; b < B; b += TW) {
        float u = user_table[users[b] * 32 + lane];
        float4 a0 = bias0, a1 = bias1;
        #pragma unroll
        for (int k = 0; k < 32; k++) {
            float uk = __shfl_sync(FULL, u, k);
            float4 q0 = w0[k * 32 + lane];
            float4 q1 = w1[k * 32 + lane];
            a0.x += uk * q0.x; a0.y += uk * q0.y; a0.z += uk * q0.z; a0.w += uk * q0.w;
            a1.x += uk * q1.x; a1.y += uk * q1.y; a1.z += uk * q1.z; a1.w += uk * q1.w;
        }
        g_Utab0[b * 32 + lane] = a0;
        g_Utab1[b * 32 + lane] = a1;
    }
}

// ---------------- main hop kernel: NP=8 paths/warp, f32 h broadcast, f32x2 FFMAs ----------------
template <int NSTEP, int STRIDE, int HOP>
__global__ __launch_bounds__(256, 2) void hop_kernel(
        const float* __restrict__ whh,
        const int* __restrict__ items,
        const int* __restrict__ lp, int B) {
    __shared__ ulonglong2 whh_sm[32 * 32];   // 16 KB: [k][lane] -> 4 gate weights
    __shared__ float h_sm[8 * NP * 32];      // 8 KB: per-warp h values [wid][p][k]

    int tid = threadIdx.x, wid = tid >> 5, lane = tid & 31;
    for (int i = tid; i < 32 * 32; i += 256) {
        int k = i >> 5, l = i & 31;
        float4 w4 = make_float4(whh[l * 32 + k], whh[(l + 32) * 32 + k],
                                whh[(l + 64) * 32 + k], whh[(l + 96) * 32 + k]);
        whh_sm[i] = *reinterpret_cast<ulonglong2*>(&w4);
    }
    __syncthreads();

    const ulonglong2* Utab = reinterpret_cast<const ulonglong2*>(HOP ? g_Utab1 : g_Utab0);
    const ulonglong2* Rtab = reinterpret_cast<const ulonglong2*>(HOP ? g_Rtab1 : g_Rtab0);
    const ulonglong2* Etab = reinterpret_cast<const ulonglong2*>(HOP ? g_Etab1 : g_Etab0);
    float* gpart = HOP ? g_part1 : g_part0;

    float*  hsw  = h_sm + wid * (NP * 32);
    float4* hsw4 = reinterpret_cast<float4*>(hsw);

    int gw = blockIdx.x * 8 + wid;
    int TW = NBLK * 8;
    int ntask = B * 2;                       // task = (b, half of 8 paths)

    for (int task = gw; task < ntask; task += TW) {
        int b = task >> 1, half = task & 1;
        int item = __ldg(&items[b]);
        const int* lpb = lp + (size_t)item * (P * STRIDE) + (size_t)half * (NP * STRIDE);

        // pack indices: 5 bits each (values in [0,32))
        u32 ipack[NP];
        #pragma unroll
        for (int p = 0; p < NP; p++) {
            u32 v = 0;
            #pragma unroll
            for (int j = 0; j < STRIDE; j++)
                v |= ((u32)__ldg(&lpb[p * STRIDE + j])) << (5 * j);
            ipack[p] = v;
        }

        ulonglong2 Ub = Utab[b * 32 + lane];   // bias already folded in

        // ---- step 0: gates = U'[b] + E[seed]; (h,c)=0 before ----
        float c[NP], h[NP];
        #pragma unroll
        for (int p = 0; p < NP; p++) {
            ulonglong2 E = Etab[(ipack[p] & 31) * 32 + lane];
            float2 glo = unpack2(fadd2(Ub.x, E.x));   // (i, f)
            float2 ghi = unpack2(fadd2(Ub.y, E.y));   // (g, o)
            c[p] = sigf(glo.x) * tanha(ghi.x);
            h[p] = sigf(ghi.y) * tanha(c[p]);
        }

        // ---- steps 1..NSTEP-1: gates = R'[rel] + T[tail] + h @ W_hh^T ----
        #pragma unroll
        for (int s = 1; s < NSTEP; s++) {
            __syncwarp();
            #pragma unroll
            for (int p = 0; p < NP; p++)
                hsw[p * 32 + lane] = h[p];           // STS.32, conflict-free
            __syncwarp();

            u64 Blo[NP], Bhi[NP];
            #pragma unroll
            for (int p = 0; p < NP; p++) {
                int ri = (ipack[p] >> (5 * (2 * s - 1))) & 31;
                int ti = (ipack[p] >> (5 * (2 * s)))     & 31;
                ulonglong2 R = Rtab[ri * 32 + lane];  // bias folded in
                ulonglong2 T = Etab[ti * 32 + lane];
                Blo[p] = fadd2(R.x, T.x);
                Bhi[p] = fadd2(R.y, T.y);
            }
            #pragma unroll
            for (int j = 0; j < 8; j++) {
                float4 h4[NP];
                #pragma unroll
                for (int p = 0; p < NP; p++) h4[p] = hsw4[p * 8 + j];  // LDS.128 broadcast
                #pragma unroll
                for (int kk = 0; kk < 4; kk++) {
                    ulonglong2 w2 = whh_sm[(4 * j + kk) * 32 + lane];
                    #pragma unroll
                    for (int p = 0; p < NP; p++) {
                        float hk = (kk == 0) ? h4[p].x : (kk == 1) ? h4[p].y
                                 : (kk == 2) ? h4[p].z : h4[p].w;
                        u64 hp = pack2(hk);
                        Blo[p] = ffma2(hp, w2.x, Blo[p]);
                        Bhi[p] = ffma2(hp, w2.y, Bhi[p]);
                    }
                }
            }
            #pragma unroll
            for (int p = 0; p < NP; p++) {
                float2 glo = unpack2(Blo[p]);   // (i, f)
                float2 ghi = unpack2(Bhi[p]);   // (g, o)
                c[p] = sigf(glo.y) * c[p] + sigf(glo.x) * tanha(ghi.x);
                h[p] = sigf(ghi.y) * tanha(c[p]);
            }
        }

        float hs = 0.f;
        #pragma unroll
        for (int p = 0; p < NP; p++) hs += h[p];
        gpart[task * 32 + lane] = hs;
    }
}

// ---------------- combine: agg matmuls, scores, sigmoid, block loss partials ----------------
__global__ __launch_bounds__(256) void combine_kernel(
        const float* __restrict__ user_table,
        const float* __restrict__ ent_table,
        const float* __restrict__ agg_w,
        const float* __restrict__ agg_b,
        const int* __restrict__ users,
        const int* __restrict__ items,
        const int* __restrict__ ratings,
        float* __restrict__ out, int B) {
    __shared__ float aggT[32 * 32];
    __shared__ float aggb_sm[32];
    __shared__ float lred[8];
    int tid = threadIdx.x;
    for (int i = tid; i < 32 * 32; i += 256) {
        int k = i >> 5, j = i & 31;
        aggT[i] = agg_w[j * 32 + k];
    }
    if (tid < 32) aggb_sm[tid] = agg_b[tid];
    __syncthreads();

    int wid = tid >> 5, lane = tid & 31;
    int gw = blockIdx.x * 8 + wid, TW = gridDim.x * 8;
    float loss_acc = 0.f;

    for (int b = gw; b < B; b += TW) {
        int item = items[b];
        int user = users[b];

        float f0 = g_part0[(b * 2 + 0) * 32 + lane] + g_part0[(b * 2 + 1) * 32 + lane];
        float f1 = g_part1[(b * 2 + 0) * 32 + lane] + g_part1[(b * 2 + 1) * 32 + lane];

        // hop-0 aggregation: emb1 = (ent[item] + final0) @ agg_w^T + agg_b
        float v = ent_table[item * 32 + lane] + f0;
        float acc = aggb_sm[lane];
        #pragma unroll
        for (int k = 0; k < 32; k++)
            acc += __shfl_sync(FULL, v, k) * aggT[k * 32 + lane];

        // hop-1 aggregation
        v = acc + f1;
        acc = aggb_sm[lane];
        #pragma unroll
        for (int k = 0; k < 32; k++)
            acc += __shfl_sync(FULL, v, k) * aggT[k * 32 + lane];

        // score = dot(u, emb2)
        float prod = user_table[user * 32 + lane] * acc;
        #pragma unroll
        for (int o = 16; o; o >>= 1) prod += __shfl_xor_sync(FULL, prod, o);

        if (lane == 0) {
            float s = prod;
            out[1 + b]     = 1.0f / (1.0f + __expf(-s));
            out[1 + B + b] = (float)item;
            float r    = (float)ratings[b];
            float ls_p = fminf(s, 0.0f)  - log1pf(__expf(-fabsf(s)));
            float ls_n = fminf(-s, 0.0f) - log1pf(__expf(-fabsf(s)));
            loss_acc += -(r * ls_p + (1.0f - r) * ls_n);
        }
    }

    if (lane == 0) lred[wid] = loss_acc;
    __syncthreads();
    if (tid == 0) {
        float s = 0.f;
        #pragma unroll
        for (int w = 0; w < 8; w++) s += lred[w];
        g_lossblk[blockIdx.x] = s;
    }
}

// ---------------- final loss reduction ----------------
__global__ void loss_kernel(float* __restrict__ out, int B, int nblk) {
    __shared__ float sm[512];
    int tid = threadIdx.x;
    float s = 0.f;
    for (int i = tid; i < nblk; i += 512) s += g_lossblk[i];
    sm[tid] = s;
    __syncthreads();
    for (int o = 256; o; o >>= 1) {
        if (tid < o) sm[tid] += sm[tid + o];
        __syncthreads();
    }
    if (tid == 0) out[0] = sm[0] / (float)B;
}

// ---------------- launch ----------------
extern "C" void kernel_launch(void* const* d_in, const int* in_sizes, int n_in,
                              void* d_out, int out_size) {
    const float* user_table = (const float*)d_in[0];
    const float* ent_table  = (const float*)d_in[1];
    const float* rel_table  = (const float*)d_in[2];
    const float* w_ih0      = (const float*)d_in[3];
    const float* w_hh0      = (const float*)d_in[4];
    const float* b_ih0      = (const float*)d_in[5];
    const float* b_hh0      = (const float*)d_in[6];
    const float* w_ih1      = (const float*)d_in[7];
    const float* w_hh1      = (const float*)d_in[8];
    const float* b_ih1      = (const float*)d_in[9];
    const float* b_hh1      = (const float*)d_in[10];
    const float* agg_w      = (const float*)d_in[11];
    const float* agg_b      = (const float*)d_in[12];
    const int*   users      = (const int*)d_in[13];
    const int*   items      = (const int*)d_in[14];
    const int*   ratings    = (const int*)d_in[15];
    const int*   lp0        = (const int*)d_in[16];
    const int*   lp1        = (const int*)d_in[17];
    float*       out        = (float*)d_out;

    int B = in_sizes[13];

    precompute_tables_kernel<<<4, 1024>>>(rel_table, ent_table, w_ih0, w_ih1,
                                          b_ih0, b_hh0, b_ih1, b_hh1);
    precompute_u_kernel<<<NBLK, 256>>>(user_table, w_ih0, w_ih1,
                                       b_ih0, b_hh0, b_ih1, b_hh1, users, B);
    hop_kernel<2, 3, 0><<<NBLK, 256>>>(w_hh0, items, lp0, B);
    hop_kernel<3, 5, 1><<<NBLK, 256>>>(w_hh1, items, lp1, B);
    combine_kernel<<<NBLK, 256>>>(user_table, ent_table, agg_w, agg_b,
                                  users, items, ratings, out, B);
    loss_kernel<<<1, 512>>>(out, B, NBLK);
}